// round 12
// baseline (speedup 1.0000x reference)
#include <cuda_runtime.h>
#include <cuda_fp16.h>

#define NLAT_IN  181
#define NLON_IN  360
#define NLAT_OUT 361
#define NLON_OUT 720
#define KSIZE    3
#define CIN      16
#define COUT     16
#define NNZ      8192
#define NBIN     (NLAT_OUT * 2)   // (hi, parity)
#define MAXB     128
#define NEIN     (NLAT_IN * KSIZE)  // 543 einsum blocks
#define NBINB    64                 // binning blocks (128 entries each)
#define NROW     (KSIZE * NLAT_IN)  // 543 xw rows
#define W2       (2 * NLON_IN)      // 720 duplicated width
#define ROWSTRIDE (2 * W2)          // uint4s per row (both halves)

// xw: [row][h][w720] as uint4 (8 fp16 ch packed, duplicated w/w+360). 12.5MB
__device__ uint4 d_xw4[NROW * ROWSTRIDE];
// Two independent bucket copies (one per channel-half k_main block).
// Entry: {meta, val_bits, orig_idx, 0}; meta = (row4<<9)|s, row4 in ROWSTRIDE units
__device__ int4 d_bk0[NBIN * MAXB];
__device__ int4 d_bk1[NBIN * MAXB];
__device__ int  d_cnt0[NBIN];   // statically zero; each k_main block resets its own
__device__ int  d_cnt1[NBIN];

// ---------------------------------------------------------------------------
// Fused: blocks 0..542 = channel-mix einsum; blocks 543..606 = atomic binning.
__global__ void __launch_bounds__(768)
k_prep(const float* __restrict__ x, const float* __restrict__ wgt,
       const int* __restrict__ ker_idx, const int* __restrict__ row_idx,
       const int* __restrict__ col_idx, const float* __restrict__ vals) {
    int t = threadIdx.x;

    if (blockIdx.x >= NEIN) {
        // ---------------- binning path ----------------
        if (t >= 128) return;
        int i   = (blockIdx.x - NEIN) * 128 + t;
        int col = col_idx[i];
        int hi  = col / NLON_OUT;
        int p   = col - hi * NLON_OUT;
        int bin = hi * 2 + (p & 1);
        int row4 = (ker_idx[i] * NLAT_IN + row_idx[i]) * ROWSTRIDE;
        int4 ent = make_int4((row4 << 9) | (p >> 1),
                             __float_as_int(vals[i]), i, 0);
        int s0 = atomicAdd(&d_cnt0[bin], 1);
        if (s0 < MAXB) d_bk0[bin * MAXB + s0] = ent;
        int s1 = atomicAdd(&d_cnt1[bin], 1);
        if (s1 < MAXB) d_bk1[bin * MAXB + s1] = ent;
        return;
    }

    // ---------------- einsum path ----------------
    // block b: tin = b % 181, k = b / 181. h=0: ch 0..7, h=1: ch 8..15.
    __shared__ float sw[COUT * CIN];  // [o][c] for this k
    int b   = blockIdx.x;
    int tin = b % NLAT_IN;
    int k   = b / NLAT_IN;
    if (t < COUT * CIN) sw[t] = wgt[t * KSIZE + k];  // wgt[o][c][k]
    __syncthreads();

    int h = (t >= 384) ? 1 : 0;
    int w = t - h * 384;
    if (w >= NLON_IN) return;

    float acc[8];
#pragma unroll
    for (int o = 0; o < 8; o++) acc[o] = 0.f;

#pragma unroll
    for (int c = 0; c < CIN; c++) {
        float xc = x[(c * NLAT_IN + tin) * NLON_IN + w];
#pragma unroll
        for (int o = 0; o < 8; o++)
            acc[o] += xc * sw[(h * 8 + o) * CIN + c];
    }
    __half2 p0 = __floats2half2_rn(acc[0], acc[1]);
    __half2 p1 = __floats2half2_rn(acc[2], acc[3]);
    __half2 p2 = __floats2half2_rn(acc[4], acc[5]);
    __half2 p3 = __floats2half2_rn(acc[6], acc[7]);
    uint4 val;
    val.x = *(unsigned*)&p0;
    val.y = *(unsigned*)&p1;
    val.z = *(unsigned*)&p2;
    val.w = *(unsigned*)&p3;
    uint4* dst = d_xw4 + (k * NLAT_IN + tin) * ROWSTRIDE + h * W2;
    dst[w] = val;
    dst[w + NLON_IN] = val;   // duplicated copy for wrap-free addressing
}

// ---------------------------------------------------------------------------
// main gather: one block per (bin, channel-half). Stages its private bucket,
// sorts by original index (determinism), precomputes per-entry BYTE base
// (incl. 360-s shift) — inner loop is base+jj*16 + LDG.128, no wrap branch.
__global__ void __launch_bounds__(384)
k_main(const float* __restrict__ bias, float* __restrict__ out) {
    __shared__ int  sidx[MAXB];
    __shared__ int2 sraw[MAXB];
    __shared__ __align__(16) int2 se[MAXB];   // sorted {byte_base, val}
    int bb = blockIdx.x;
    int b  = bb >> 1;          // bin
    int h  = bb & 1;           // channel half
    int hi = b >> 1;
    int q  = b & 1;
    int tid = threadIdx.x;

    int* cntp = h ? d_cnt1 : d_cnt0;
    const int4* bk = (h ? d_bk1 : d_bk0) + b * MAXB;

    int cnt = cntp[b];
    if (cnt > MAXB) cnt = MAXB;
    if (tid < cnt) {
        int4 e = bk[tid];
        int s    = e.x & 511;
        int row4 = e.x >> 9;
        sraw[tid] = make_int2((row4 + NLON_IN - s) * 16, e.y);
        sidx[tid] = e.z;
    }
    __syncthreads();
    if (tid == 0) cntp[b] = 0;          // reset for next graph replay
    if (tid < cnt) {
        int my = sidx[tid];
        int r = 0;
        for (int j = 0; j < cnt; j++) r += (sidx[j] < my);
        se[r] = sraw[tid];
    }
    __syncthreads();

    int jj = tid;
    if (jj >= NLON_IN) return;

    const char* __restrict__ xb =
        (const char*)d_xw4 + h * (W2 * 16) + jj * 16;
    float acc[8];
#pragma unroll
    for (int o = 0; o < 8; o++) acc[o] = 0.f;

    const int4* se4 = (const int4*)se;
    int e = 0;
    for (; e + 3 < cnt; e += 4) {
        int4 A = se4[e >> 1];
        int4 B = se4[(e >> 1) + 1];
        uint4 d0 = *(const uint4*)(xb + A.x);
        uint4 d1 = *(const uint4*)(xb + A.z);
        uint4 d2 = *(const uint4*)(xb + B.x);
        uint4 d3 = *(const uint4*)(xb + B.z);
        float v0 = __int_as_float(A.y), v1 = __int_as_float(A.w);
        float v2 = __int_as_float(B.y), v3 = __int_as_float(B.w);
#pragma unroll
        for (int j = 0; j < 4; j++) {
            float2 f0 = __half22float2(*(const __half2*)(&d0.x + j));
            float2 f1 = __half22float2(*(const __half2*)(&d1.x + j));
            float2 f2 = __half22float2(*(const __half2*)(&d2.x + j));
            float2 f3 = __half22float2(*(const __half2*)(&d3.x + j));
            acc[2 * j]     += v0 * f0.x + v1 * f1.x + v2 * f2.x + v3 * f3.x;
            acc[2 * j + 1] += v0 * f0.y + v1 * f1.y + v2 * f2.y + v3 * f3.y;
        }
    }
    for (; e < cnt; e++) {
        int2 ev = se[e];
        float v = __int_as_float(ev.y);
        uint4 dd = *(const uint4*)(xb + ev.x);
#pragma unroll
        for (int j = 0; j < 4; j++) {
            float2 f = __half22float2(*(const __half2*)(&dd.x + j));
            acc[2 * j]     += v * f.x;
            acc[2 * j + 1] += v * f.y;
        }
    }

    int lon = q + 2 * jj;
    const int cs = NLAT_OUT * NLON_OUT;
    float* dst = out + (h * 8) * cs + hi * NLON_OUT + lon;
#pragma unroll
    for (int o = 0; o < 8; o++) dst[o * cs] = acc[o] + bias[h * 8 + o];
}

// ---------------------------------------------------------------------------
extern "C" void kernel_launch(void* const* d_in, const int* in_sizes, int n_in,
                              void* d_out, int out_size) {
    const float* x       = (const float*)d_in[0];
    const float* weight  = (const float*)d_in[1];
    const float* bias    = (const float*)d_in[2];
    const int*   ker_idx = (const int*)d_in[3];
    const int*   row_idx = (const int*)d_in[4];
    const int*   col_idx = (const int*)d_in[5];
    const float* vals    = (const float*)d_in[6];
    float* out = (float*)d_out;

    (void)in_sizes; (void)n_in; (void)out_size;

    k_prep<<<NEIN + NBINB, 768>>>(x, weight, ker_idx, row_idx, col_idx, vals);
    k_main<<<NBIN * 2, 384>>>(bias, out);
}

// round 13
// speedup vs baseline: 1.0260x; 1.0260x over previous
#include <cuda_runtime.h>
#include <cuda_fp16.h>

#define NLAT_IN  181
#define NLON_IN  360
#define NLAT_OUT 361
#define NLON_OUT 720
#define KSIZE    3
#define CIN      16
#define COUT     16
#define NNZ      8192
#define NBIN     (NLAT_OUT * 2)   // (hi, parity)
#define MAXB     128
#define NEIN     (NLAT_IN * KSIZE)  // 543 einsum blocks
#define NBINB    64                 // binning blocks (128 entries each)
#define NROW     (KSIZE * NLAT_IN)  // 543 xw rows

// xw: [row][h][w] as uint4 (8 fp16 channels packed). 6.25MB
__device__ uint4 d_xw4[NROW * 2 * NLON_IN];
// Two independent bucket copies (one per channel-half k_main block).
// Entry: {meta, val_bits, orig_idx, 0}; meta = (row4<<9)|s
__device__ int4 d_bk0[NBIN * MAXB];
__device__ int4 d_bk1[NBIN * MAXB];
__device__ int  d_cnt0[NBIN];   // statically zero; each k_main block resets its own
__device__ int  d_cnt1[NBIN];

// ---------------------------------------------------------------------------
// Fused: blocks 0..542 = channel-mix einsum; blocks 543..606 = atomic binning.
__global__ void __launch_bounds__(768)
k_prep(const float* __restrict__ x, const float* __restrict__ wgt,
       const int* __restrict__ ker_idx, const int* __restrict__ row_idx,
       const int* __restrict__ col_idx, const float* __restrict__ vals) {
    int t = threadIdx.x;

    if (blockIdx.x >= NEIN) {
        // ---------------- binning path ----------------
        if (t >= 128) return;
        int i   = (blockIdx.x - NEIN) * 128 + t;
        int col = col_idx[i];
        int hi  = col / NLON_OUT;
        int p   = col - hi * NLON_OUT;
        int bin = hi * 2 + (p & 1);
        int row4 = (ker_idx[i] * NLAT_IN + row_idx[i]) * (2 * NLON_IN);
        int4 ent = make_int4((row4 << 9) | (p >> 1),
                             __float_as_int(vals[i]), i, 0);
        int s0 = atomicAdd(&d_cnt0[bin], 1);
        if (s0 < MAXB) d_bk0[bin * MAXB + s0] = ent;
        int s1 = atomicAdd(&d_cnt1[bin], 1);
        if (s1 < MAXB) d_bk1[bin * MAXB + s1] = ent;
        return;
    }

    // ---------------- einsum path ----------------
    // block b: tin = b % 181, k = b / 181. h=0: ch 0..7, h=1: ch 8..15.
    __shared__ float sw[COUT * CIN];  // [o][c] for this k
    int b   = blockIdx.x;
    int tin = b % NLAT_IN;
    int k   = b / NLAT_IN;
    if (t < COUT * CIN) sw[t] = wgt[t * KSIZE + k];  // wgt[o][c][k]
    __syncthreads();

    int h = (t >= 384) ? 1 : 0;
    int w = t - h * 384;
    if (w >= NLON_IN) return;

    float acc[8];
#pragma unroll
    for (int o = 0; o < 8; o++) acc[o] = 0.f;

#pragma unroll
    for (int c = 0; c < CIN; c++) {
        float xc = x[(c * NLAT_IN + tin) * NLON_IN + w];
#pragma unroll
        for (int o = 0; o < 8; o++)
            acc[o] += xc * sw[(h * 8 + o) * CIN + c];
    }
    __half2 p0 = __floats2half2_rn(acc[0], acc[1]);
    __half2 p1 = __floats2half2_rn(acc[2], acc[3]);
    __half2 p2 = __floats2half2_rn(acc[4], acc[5]);
    __half2 p3 = __floats2half2_rn(acc[6], acc[7]);
    uint4 val;
    val.x = *(unsigned*)&p0;
    val.y = *(unsigned*)&p1;
    val.z = *(unsigned*)&p2;
    val.w = *(unsigned*)&p3;
    d_xw4[(k * NLAT_IN + tin) * (2 * NLON_IN) + h * NLON_IN + w] = val;
}

// ---------------------------------------------------------------------------
// main gather: one block per (bin, channel-half); 192 threads. Thread jj
// handles lons q+2*jj and q+2*(jj+180): entry decode amortized over 2 lons,
// 8 LDG.128 in flight (unroll 4 entries x 2 lons). Bucket padded to a
// multiple of 4 with zero-val sentinels -> no tail loop.
__global__ void __launch_bounds__(192, 5)
k_main(const float* __restrict__ bias, float* __restrict__ out) {
    __shared__ int  sidx[MAXB];
    __shared__ int2 sraw[MAXB];
    __shared__ __align__(16) int2 se[MAXB];   // sorted {meta, val}
    int bb = blockIdx.x;
    int b  = bb >> 1;          // bin
    int h  = bb & 1;           // channel half
    int hi = b >> 1;
    int q  = b & 1;
    int tid = threadIdx.x;

    int* cntp = h ? d_cnt1 : d_cnt0;
    const int4* bk = (h ? d_bk1 : d_bk0) + b * MAXB;

    int cnt = cntp[b];
    if (cnt > MAXB) cnt = MAXB;
    int cntP = (cnt + 3) & ~3;
    if (tid < cnt) {
        int4 e = bk[tid];
        sraw[tid] = make_int2(e.x, e.y);
        sidx[tid] = e.z;
    }
    __syncthreads();
    if (tid == 0) cntp[b] = 0;          // reset for next graph replay
    if (tid < cnt) {
        int my = sidx[tid];
        int r = 0;
        for (int j = 0; j < cnt; j++) r += (sidx[j] < my);
        se[r] = sraw[tid];
    }
    if (tid >= cnt && tid < cntP) se[tid] = make_int2(0, 0);  // sentinel
    __syncthreads();

    int jj = tid;
    if (jj >= 180) return;

    const uint4* __restrict__ xbase = d_xw4 + h * NLON_IN;
    float acc[16];                    // [lon-half][8 ch]
#pragma unroll
    for (int o = 0; o < 16; o++) acc[o] = 0.f;

    const int4* se4 = (const int4*)se;
    for (int e = 0; e < cntP; e += 4) {
        int4 A = se4[e >> 1];
        int4 B = se4[(e >> 1) + 1];
        int m0 = A.x, m1 = A.z, m2 = B.x, m3 = B.z;
        float v0 = __int_as_float(A.y), v1 = __int_as_float(A.w);
        float v2 = __int_as_float(B.y), v3 = __int_as_float(B.w);
        int s0 = m0 & 511, s1 = m1 & 511, s2 = m2 & 511, s3 = m3 & 511;
        int wa0 = jj - s0; if (wa0 < 0) wa0 += NLON_IN;
        int wa1 = jj - s1; if (wa1 < 0) wa1 += NLON_IN;
        int wa2 = jj - s2; if (wa2 < 0) wa2 += NLON_IN;
        int wa3 = jj - s3; if (wa3 < 0) wa3 += NLON_IN;
        int wb0 = wa0 + 180; if (wb0 >= NLON_IN) wb0 -= NLON_IN;
        int wb1 = wa1 + 180; if (wb1 >= NLON_IN) wb1 -= NLON_IN;
        int wb2 = wa2 + 180; if (wb2 >= NLON_IN) wb2 -= NLON_IN;
        int wb3 = wa3 + 180; if (wb3 >= NLON_IN) wb3 -= NLON_IN;
        uint4 da0 = xbase[(m0 >> 9) + wa0];
        uint4 db0 = xbase[(m0 >> 9) + wb0];
        uint4 da1 = xbase[(m1 >> 9) + wa1];
        uint4 db1 = xbase[(m1 >> 9) + wb1];
        uint4 da2 = xbase[(m2 >> 9) + wa2];
        uint4 db2 = xbase[(m2 >> 9) + wb2];
        uint4 da3 = xbase[(m3 >> 9) + wa3];
        uint4 db3 = xbase[(m3 >> 9) + wb3];
#pragma unroll
        for (int j = 0; j < 4; j++) {
            float2 fa0 = __half22float2(*(const __half2*)(&da0.x + j));
            float2 fa1 = __half22float2(*(const __half2*)(&da1.x + j));
            float2 fa2 = __half22float2(*(const __half2*)(&da2.x + j));
            float2 fa3 = __half22float2(*(const __half2*)(&da3.x + j));
            acc[2 * j]     += v0 * fa0.x + v1 * fa1.x + v2 * fa2.x + v3 * fa3.x;
            acc[2 * j + 1] += v0 * fa0.y + v1 * fa1.y + v2 * fa2.y + v3 * fa3.y;
            float2 fb0 = __half22float2(*(const __half2*)(&db0.x + j));
            float2 fb1 = __half22float2(*(const __half2*)(&db1.x + j));
            float2 fb2 = __half22float2(*(const __half2*)(&db2.x + j));
            float2 fb3 = __half22float2(*(const __half2*)(&db3.x + j));
            acc[8 + 2 * j]     += v0 * fb0.x + v1 * fb1.x + v2 * fb2.x + v3 * fb3.x;
            acc[8 + 2 * j + 1] += v0 * fb0.y + v1 * fb1.y + v2 * fb2.y + v3 * fb3.y;
        }
    }

    int lon0 = q + 2 * jj;
    int lon1 = lon0 + 360;
    const int cs = NLAT_OUT * NLON_OUT;
    float* dst0 = out + (h * 8) * cs + hi * NLON_OUT + lon0;
    float* dst1 = dst0 + 360;
#pragma unroll
    for (int o = 0; o < 8; o++) {
        float bv = bias[h * 8 + o];
        dst0[o * cs] = acc[o] + bv;
        dst1[o * cs] = acc[8 + o] + bv;
    }
}

// ---------------------------------------------------------------------------
extern "C" void kernel_launch(void* const* d_in, const int* in_sizes, int n_in,
                              void* d_out, int out_size) {
    const float* x       = (const float*)d_in[0];
    const float* weight  = (const float*)d_in[1];
    const float* bias    = (const float*)d_in[2];
    const int*   ker_idx = (const int*)d_in[3];
    const int*   row_idx = (const int*)d_in[4];
    const int*   col_idx = (const int*)d_in[5];
    const float* vals    = (const float*)d_in[6];
    float* out = (float*)d_out;

    (void)in_sizes; (void)n_in; (void)out_size;

    k_prep<<<NEIN + NBINB, 768>>>(x, weight, ker_idx, row_idx, col_idx, vals);
    k_main<<<NBIN * 2, 192>>>(bias, out);
}